// round 1
// baseline (speedup 1.0000x reference)
#include <cuda_runtime.h>
#include <cstddef>

// Depthwise 4x4 FIR conv, stride-2 downsample, zero pad (1,1,1,1).
// x: (16, 512, 64, 64) f32  -> out: (16, 512, 32, 32) f32
// kernel: (4,4) f32, applied flipped (true convolution), per reference.
//
// One CTA per (n,c) plane. Stage 64x64 plane into smem with 1-px zero halo
// (66 rows x 68-float pitch for alignment), 256 threads, each thread computes
// 4 horizontally-adjacent outputs and writes one float4.

#define IN_H   64
#define IN_W   64
#define OUT_H  32
#define OUT_W  32
#define S_ROWS 66
#define S_PITCH 68   // floats; keeps float2 alignment (even) and decorrelates banks

__global__ __launch_bounds__(256, 8)
void upfirdn_down2_kernel(const float* __restrict__ x,
                          const float* __restrict__ k,
                          float* __restrict__ out,
                          int n_planes)
{
    __shared__ float s[S_ROWS * S_PITCH];
    __shared__ float wk[16];

    const int plane = blockIdx.x;
    if (plane >= n_planes) return;
    const int tid = threadIdx.x;

    if (tid < 16) wk[tid] = k[tid];

    // Zero entire tile (handles halo).
    #pragma unroll
    for (int i = tid; i < S_ROWS * S_PITCH; i += 256) s[i] = 0.0f;
    __syncthreads();

    // Fill interior: 4096 floats via float4 loads (coalesced 16B/thread/iter).
    const float* __restrict__ xin = x + (size_t)plane * (IN_H * IN_W);
    #pragma unroll
    for (int i = tid; i < (IN_H * IN_W) / 4; i += 256) {
        float4 v = __ldg((const float4*)xin + i);
        int lin = i * 4;
        int y = lin >> 6;        // /64
        int xc = lin & 63;       // %64
        float* dst = &s[(y + 1) * S_PITCH + (xc + 1)];
        dst[0] = v.x; dst[1] = v.y; dst[2] = v.z; dst[3] = v.w;
    }
    __syncthreads();

    // Flipped weights into registers (true convolution).
    float w[4][4];
    #pragma unroll
    for (int i = 0; i < 4; i++)
        #pragma unroll
        for (int j = 0; j < 4; j++)
            w[i][j] = wk[(3 - i) * 4 + (3 - j)];

    // Each thread: output row oy, 4 adjacent columns starting at oxb.
    const int oy  = tid >> 3;         // 0..31
    const int oxb = (tid & 7) * 4;    // 0,4,...,28

    float acc0 = 0.f, acc1 = 0.f, acc2 = 0.f, acc3 = 0.f;

    #pragma unroll
    for (int i = 0; i < 4; i++) {
        // Window rows: input row (2*oy - 1 + i) -> smem row (2*oy + i).
        const float* row = &s[(2 * oy + i) * S_PITCH + 2 * oxb];
        // Need cols [0..9] of this window strip: 5x float2 (even-aligned).
        float v[10];
        #pragma unroll
        for (int t = 0; t < 5; t++) {
            float2 p = *(const float2*)&row[2 * t];
            v[2 * t]     = p.x;
            v[2 * t + 1] = p.y;
        }
        #pragma unroll
        for (int j = 0; j < 4; j++) {
            const float wij = w[i][j];
            acc0 = fmaf(v[0 + j], wij, acc0);
            acc1 = fmaf(v[2 + j], wij, acc1);
            acc2 = fmaf(v[4 + j], wij, acc2);
            acc3 = fmaf(v[6 + j], wij, acc3);
        }
    }

    float4 o = make_float4(acc0, acc1, acc2, acc3);
    *(float4*)(out + (size_t)plane * (OUT_H * OUT_W) + oy * OUT_W + oxb) = o;
}

extern "C" void kernel_launch(void* const* d_in, const int* in_sizes, int n_in,
                              void* d_out, int out_size)
{
    // Inputs: x (16*512*64*64 = 33554432 f32), kernel (16 f32). Identify by size
    // defensively in case of metadata reordering.
    int xi = 0, ki = 1;
    if (n_in >= 2 && in_sizes[0] < in_sizes[1]) { xi = 1; ki = 0; }

    const float* x = (const float*)d_in[xi];
    const float* k = (const float*)d_in[ki];
    float* out = (float*)d_out;

    const int n_planes = in_sizes[xi] / (IN_H * IN_W);  // 16*512 = 8192

    upfirdn_down2_kernel<<<n_planes, 256>>>(x, k, out, n_planes);
}

// round 2
// speedup vs baseline: 1.6494x; 1.6494x over previous
#include <cuda_runtime.h>
#include <cstddef>

// Depthwise 4x4 FIR conv, stride-2 downsample, zero pad (1,1,1,1).
// x: (16,512,64,64) f32 -> out: (16,512,32,32) f32. kernel: (4,4) f32, flipped.
//
// No shared memory. Each thread computes a 2x4 output block (rows 2b,2b+1,
// cols 4c..4c+3) reading 6 input rows x 10 cols. Core 8 cols come from two
// aligned LDG.128; the +/-1 halo columns come from neighbor lanes via
// __shfl with width=8 (plane edges -> zero pad). One CTA = 256 threads =
// 2 planes. No barriers, no LDS/STS.

#define IN_W 64
#define OUT_W 32

__global__ __launch_bounds__(256)
void upfirdn_down2_kernel(const float* __restrict__ x,
                          const float* __restrict__ k,
                          float* __restrict__ out,
                          int n_planes)
{
    const int tid = threadIdx.x;
    const int c   = tid & 7;          // col group: output cols 4c..4c+3
    const int b   = (tid >> 3) & 15;  // row block: output rows 2b, 2b+1
    const int pl  = tid >> 7;         // plane within CTA (0/1)
    const int plane = blockIdx.x * 2 + pl;
    if (plane >= n_planes) return;

    // Flipped weights (true convolution), broadcast loads.
    float w[4][4];
    #pragma unroll
    for (int i = 0; i < 4; i++)
        #pragma unroll
        for (int j = 0; j < 4; j++)
            w[i][j] = __ldg(&k[(3 - i) * 4 + (3 - j)]);

    const float4* __restrict__ xin =
        (const float4*)(x + (size_t)plane * (IN_W * IN_W));

    float acc0[4] = {0.f, 0.f, 0.f, 0.f};
    float acc1[4] = {0.f, 0.f, 0.f, 0.f};

    #pragma unroll
    for (int j = 0; j < 6; j++) {
        const int r = 4 * b - 1 + j;           // input row
        float4 a  = make_float4(0.f, 0.f, 0.f, 0.f);
        float4 bb = a;
        if (r >= 0 && r < IN_W) {              // zero rows at plane edges
            a  = __ldg(xin + (size_t)r * 16 + c * 2);
            bb = __ldg(xin + (size_t)r * 16 + c * 2 + 1);
        }
        float f0 = a.x, f7 = bb.w;
        // Halo columns from neighbor lanes (segment width 8 == row of col-groups).
        float vl = __shfl_up_sync(0xffffffffu, f7, 1, 8);   // col 8c-1
        float vr = __shfl_down_sync(0xffffffffu, f0, 1, 8); // col 8c+8
        if (c == 0) vl = 0.f;   // left plane edge (zero pad)
        if (c == 7) vr = 0.f;   // right plane edge (zero pad)

        float v[10];
        v[0] = vl;
        v[1] = a.x;  v[2] = a.y;  v[3] = a.z;  v[4] = a.w;
        v[5] = bb.x; v[6] = bb.y; v[7] = bb.z; v[8] = bb.w;
        v[9] = vr;

        // Row r = 2*(2b)-1 + j  -> tap j for output row 2b (j in [0,4))
        if (j < 4) {
            #pragma unroll
            for (int xq = 0; xq < 4; xq++)
                #pragma unroll
                for (int t = 0; t < 4; t++)
                    acc0[xq] = fmaf(v[2 * xq + t], w[j][t], acc0[xq]);
        }
        // Row r = 2*(2b+1)-1 + (j-2) -> tap j-2 for output row 2b+1 (j in [2,6))
        if (j >= 2) {
            #pragma unroll
            for (int xq = 0; xq < 4; xq++)
                #pragma unroll
                for (int t = 0; t < 4; t++)
                    acc1[xq] = fmaf(v[2 * xq + t], w[j - 2][t], acc1[xq]);
        }
    }

    float* o = out + (size_t)plane * (OUT_W * OUT_W) + (2 * b) * OUT_W + c * 4;
    *(float4*)o           = make_float4(acc0[0], acc0[1], acc0[2], acc0[3]);
    *(float4*)(o + OUT_W) = make_float4(acc1[0], acc1[1], acc1[2], acc1[3]);
}

extern "C" void kernel_launch(void* const* d_in, const int* in_sizes, int n_in,
                              void* d_out, int out_size)
{
    int xi = 0, ki = 1;
    if (n_in >= 2 && in_sizes[0] < in_sizes[1]) { xi = 1; ki = 0; }

    const float* x = (const float*)d_in[xi];
    const float* k = (const float*)d_in[ki];
    float* out = (float*)d_out;

    const int n_planes = in_sizes[xi] / (IN_W * IN_W);   // 8192
    const int blocks = (n_planes + 1) / 2;               // 2 planes per CTA

    upfirdn_down2_kernel<<<blocks, 256>>>(x, k, out, n_planes);
}